// round 1
// baseline (speedup 1.0000x reference)
#include <cuda_runtime.h>
#include <math.h>

#define THRESH 1e-4f
#define MAXBP  8192
#define L1     32
#define W1     64
#define L2     16
#define BIGL   0x40000000

// Scratch (no allocations allowed) -------------------------------------------
__device__ int g_anom_n;
__device__ int g_anom_p[MAXBP];
__device__ int g_anom_l[MAXBP];
__device__ int g_K;
__device__ int g_P[MAXBP];
__device__ int g_Q[MAXBP];

// K0: zero the anomaly counter (graph replays reuse scratch) -----------------
__global__ void k0_zero() { g_anom_n = 0; }

// K1: chunked h scan with warm-up. Contraction |w2+2w4*h|~0.2/step makes a
// 64-step warm-up bitwise-exact. Writes Z[t+1] = h after step t.
__global__ void k1_z(const float* __restrict__ X, const float* __restrict__ pr,
                     float* __restrict__ Z, int T) {
    long long c = (long long)blockIdx.x * blockDim.x + threadIdx.x;
    long long s = c * L1;
    if (s >= (long long)(T - 1)) return;
    float w1 = (float)tanh((double)pr[0]);
    float w2 = (float)tanh((double)pr[1]);
    float w3 = pr[2], w4 = pr[3];
    int si = (int)s;
    int t0 = si - W1; if (t0 < 0) t0 = 0;
    int e  = si + L1; if (e > T - 1) e = T - 1;
    if (si == 0) Z[0] = 0.f;
    float h = 0.f;
    for (int t = t0; t < e; ++t) {
        float x  = X[t];
        float cc = fmaf(w3, x * x, w1 * x);
        float u  = fmaf(w4, h, w2);        // 8-cycle critical path per step
        h = fmaf(h, u, cc);
        if (t >= si) Z[t + 1] = h;
    }
}

// K2: for every candidate window start p, compute the window length with the
// EXACT fp32 product semantics of the main loop. Record anomalies (len != 6).
__global__ void k2_anom(const float* __restrict__ Z, const float* __restrict__ pr,
                        int T) {
    int p = blockIdx.x * blockDim.x + threadIdx.x;
    if (p >= T - 1) return;
    float w2   = (float)tanh((double)pr[1]);
    float w4_2 = 2.0f * pr[3];
    float d = 1.f; int l = -1;
#pragma unroll 1
    for (int j = 0; j < 32; ++j) {
        int t = p + j;
        if (t >= T - 1) break;                       // window runs past data end
        float a = __fadd_rn(w2, __fmul_rn(w4_2, Z[t]));
        d = __fmul_rn(d, fabsf(a));
        if (d < THRESH) { l = j + 1; break; }
    }
    if (l != 6) {
        int i = atomicAdd(&g_anom_n, 1);
        if (i < MAXBP) { g_anom_p[i] = p; g_anom_l[i] = (l < 0) ? BIGL : l; }
    }
}

// K3: single thread. Sort anomalies, walk the reset orbit from step 0
// (default stride 6), keep only anomalies actually on the orbit -> breakpoints.
__global__ void k3_walk() {
    int n = g_anom_n; if (n > MAXBP) n = MAXBP;
    for (int i = 1; i < n; ++i) {                    // insertion sort (n ~ 0-10)
        int p = g_anom_p[i], l = g_anom_l[i], j = i - 1;
        while (j >= 0 && g_anom_p[j] > p) {
            g_anom_p[j + 1] = g_anom_p[j]; g_anom_l[j + 1] = g_anom_l[j]; --j;
        }
        g_anom_p[j + 1] = p; g_anom_l[j + 1] = l;
    }
    int pos = 0, K = 0;
    for (int i = 0; i < n && K < MAXBP; ++i) {
        int p = g_anom_p[i];
        if (p < pos) continue;
        if ((p - pos) % 6 != 0) continue;            // not reachable by orbit
        int l = g_anom_l[i];
        g_P[K] = p;
        if (l >= BIGL) { g_Q[K] = 0x7fffffff; ++K; break; }  // final open window
        g_Q[K] = p + l; pos = p + l; ++K;
    }
    g_K = K;
}

// Given step s, return the start of the reset window containing s.
__device__ __forceinline__ int window_start(int s) {
    int K = g_K;
    if (K == 0 || s < g_P[0]) return s - s % 6;
    int lo = 0, hi = K - 1;
    while (lo < hi) {                                 // last k with P[k] <= s
        int mid = (lo + hi + 1) >> 1;
        if (g_P[mid] <= s) lo = mid; else hi = mid - 1;
    }
    int q = g_Q[lo];
    if (s < q) return g_P[lo];
    int r = s - q;
    return q + (r - r % 6);
}

// K4: main. Each thread rebuilds J/H carries from the window start (<= ~8
// steps) then emits L2 steps of outputs. Decay recurrence is bit-identical to K2.
__global__ void k4_main(const float* __restrict__ X, const float* __restrict__ Z,
                        const float* __restrict__ pr,
                        float* __restrict__ outJ, float* __restrict__ outH, int T) {
    int c = blockIdx.x * blockDim.x + threadIdx.x;
    int s = c * L2;
    if (c == 0) {                                     // row 0 of J and H = 0
        ((float4*)outJ)[0] = make_float4(0, 0, 0, 0);
        float4 z4 = make_float4(0, 0, 0, 0);
        float4* Hp = (float4*)outH;
        Hp[0] = z4; Hp[1] = z4; Hp[2] = z4; Hp[3] = z4;
    }
    if (s >= T - 1) return;

    float w1 = (float)tanh((double)pr[0]);
    float w2 = (float)tanh((double)pr[1]);
    float w3 = pr[2], w4 = pr[3];
    (void)w1; (void)w3;
    float dt1  = 1.f - w1 * w1,  dt2  = 1.f - w2 * w2;
    float d2t1 = -2.f * w1 * dt1, d2t2 = -2.f * w2 * dt2;
    float w4_2 = 2.f * w4;

    int w = window_start(s);
    int e = s + L2; if (e > T - 1) e = T - 1;

    float J0 = 0, J1 = 0, J2 = 0, J3 = 0;
    float H00 = 0, H01 = 0, H02 = 0, H03 = 0, H11 = 0;
    float H12 = 0, H13 = 0, H22 = 0, H23 = 0, H33 = 0;
    float dec = 1.f;

#pragma unroll 1
    for (int t = w; t < e; ++t) {
        float x = X[t], h = Z[t];
        float a  = __fadd_rn(w2, __fmul_rn(w4_2, h));     // df_dh (exact match K2)
        float dn = __fmul_rn(dec, fabsf(a));
        bool  rs = dn < THRESH;
        float g3 = 2.f * h;
        float nJ0 = fmaf(a, J0, x * dt1);
        float nJ1 = fmaf(a, J1, h * dt2);
        float nJ2 = fmaf(a, J2, x * x);
        float nJ3 = fmaf(a, J3, h * h);
        float nH00 = fmaf(a, H00, x * d2t1);
        float nH01 = fmaf(a, H01, dt2 * J0);
        float nH02 = a * H02;
        float nH03 = fmaf(a, H03, g3 * J0);
        float nH11 = fmaf(a, H11, fmaf(2.f * dt2, J1, h * d2t2));
        float nH12 = fmaf(a, H12, dt2 * J2);
        float nH13 = fmaf(a, H13, fmaf(dt2, J3, g3 * J1));
        float nH22 = a * H22;
        float nH23 = fmaf(a, H23, g3 * J2);
        float nH33 = fmaf(a, H33, (2.f * g3) * J3);
        if (rs) {
            J0 = J1 = J2 = J3 = 0.f;
            H00 = H01 = H02 = H03 = H11 = 0.f;
            H12 = H13 = H22 = H23 = H33 = 0.f;
            dec = 1.f;
        } else {
            J0 = nJ0; J1 = nJ1; J2 = nJ2; J3 = nJ3;
            H00 = nH00; H01 = nH01; H02 = nH02; H03 = nH03; H11 = nH11;
            H12 = nH12; H13 = nH13; H22 = nH22; H23 = nH23; H33 = nH33;
            dec = dn;
        }
        if (t >= s) {                                   // emit post-reset values
            int o = t + 1;
            ((float4*)outJ)[o] = make_float4(J0, J1, J2, J3);
            float4* Hp = (float4*)(outH + 16 * (size_t)o);
            Hp[0] = make_float4(H00, H01, H02, H03);
            Hp[1] = make_float4(H01, H11, H12, H13);
            Hp[2] = make_float4(H02, H12, H22, H23);
            Hp[3] = make_float4(H03, H13, H23, H33);
        }
    }
}

extern "C" void kernel_launch(void* const* d_in, const int* in_sizes, int n_in,
                              void* d_out, int out_size) {
    const float* X  = (const float*)d_in[0];
    const float* pr = (const float*)d_in[1];
    int T = in_sizes[0];
    float* out = (float*)d_out;
    float* Z = out;                       // [T]
    float* J = out + (size_t)T;           // [T,4]
    float* H = out + (size_t)5 * T;       // [T,4,4]

    int nsteps = T - 1;
    k0_zero<<<1, 1>>>();
    int c1 = (nsteps + L1 - 1) / L1;
    k1_z<<<(c1 + 255) / 256, 256>>>(X, pr, Z, T);
    k2_anom<<<(nsteps + 255) / 256, 256>>>(Z, pr, T);
    k3_walk<<<1, 1>>>();
    int c4 = (nsteps + L2 - 1) / L2;
    k4_main<<<(c4 + 255) / 256, 256>>>(X, Z, pr, J, H, T);
}